// round 3
// baseline (speedup 1.0000x reference)
#include <cuda_runtime.h>
#include <math.h>

#define NNODES 50000
#define NHALF  25000
#define NEDGES 400000
#define F512   512
#define H8     8

// ---------------- scratch (device globals; no allocation allowed) ----------------
__device__ float g_h0[NNODES * 64];
__device__ float g_ft[NNODES * F512];
__device__ float g_h1[NNODES * F512];
__device__ float g_el[NNODES * H8];
__device__ float g_er[NNODES * H8];
__device__ float g_e[NEDGES * H8];     // e -> exp -> alpha (in place), reused per layer
__device__ float g_ft2[NNODES * 16];
__device__ float g_res2[NNODES * 16];
__device__ int   g_deg[NNODES];
__device__ int   g_cur[NNODES];
__device__ int   g_rowoff[NNODES + 1];
__device__ int   g_eid[NEDGES];

// device-side scratch-buffer selector (no host-side symbol-address API needed)
__device__ __forceinline__ float* bufsel(int id) {
    switch (id) {
        case 0: return g_h0;
        case 1: return g_ft;
        case 2: return g_h1;
    }
    return nullptr;
}

// ---------------- CSR build ----------------
__global__ void k_zero_counts() {
    int i = blockIdx.x * blockDim.x + threadIdx.x;
    if (i < NNODES) { g_deg[i] = 0; g_cur[i] = 0; }
}

__global__ void k_count(const int* __restrict__ dst) {
    int i = blockIdx.x * blockDim.x + threadIdx.x;
    if (i < NEDGES) {
        int d = dst[i];
        if (d >= 0 && d < NNODES) atomicAdd(&g_deg[d], 1);
    }
}

// single-block exclusive scan over g_deg -> g_rowoff
__global__ void k_scan() {
    __shared__ int warp_sums[32];
    __shared__ int carry_sh;
    int t = threadIdx.x;
    if (t == 0) carry_sh = 0;
    __syncthreads();
    for (int base = 0; base < NNODES; base += 1024) {
        int i = base + t;
        int v = (i < NNODES) ? g_deg[i] : 0;
        int x = v;
        #pragma unroll
        for (int o = 1; o < 32; o <<= 1) {
            int y = __shfl_up_sync(0xffffffffu, x, o);
            if ((t & 31) >= o) x += y;
        }
        if ((t & 31) == 31) warp_sums[t >> 5] = x;
        __syncthreads();
        if (t < 32) {
            int w = warp_sums[t];
            #pragma unroll
            for (int o = 1; o < 32; o <<= 1) {
                int y = __shfl_up_sync(0xffffffffu, w, o);
                if (t >= o) w += y;
            }
            warp_sums[t] = w;
        }
        __syncthreads();
        int pref = (t >= 32) ? warp_sums[(t >> 5) - 1] : 0;
        int incl = x + pref;
        int carry = carry_sh;
        if (i < NNODES) g_rowoff[i] = carry + incl - v;   // exclusive
        __syncthreads();
        if (t == 1023) carry_sh = carry + incl;
        __syncthreads();
    }
    if (t == 0) g_rowoff[NNODES] = carry_sh;
}

__global__ void k_scatter(const int* __restrict__ dst) {
    int i = blockIdx.x * blockDim.x + threadIdx.x;
    if (i < NEDGES) {
        int d = dst[i];
        if (d >= 0 && d < NNODES) {
            int p = g_rowoff[d] + atomicAdd(&g_cur[d], 1);
            g_eid[p] = i;
        }
    }
}

// per-segment insertion sort by edge id -> fully deterministic summation order
__global__ void k_sortseg() {
    int n = blockIdx.x * blockDim.x + threadIdx.x;
    if (n >= NNODES) return;
    int s = g_rowoff[n], e = g_rowoff[n + 1];
    for (int i = s + 1; i < e; i++) {
        int key = g_eid[i];
        int j = i - 1;
        while (j >= s && g_eid[j] > key) { g_eid[j + 1] = g_eid[j]; j--; }
        g_eid[j + 1] = key;
    }
}

// ---------------- GEMM: C[M,N] = A[M,K] @ B[K,N] (+ bias per column) ----------------
// 64x64 tile, BK=16, 256 threads, 4x4 per thread. K%16==0, N%64==0 required.
__global__ __launch_bounds__(256) void gemm_kernel(
    const float* __restrict__ Aext, int a_id,
    float* __restrict__ Cext, int c_id, size_t c_off,
    const float* __restrict__ B,
    int M, int N, int K, const float* __restrict__ bias)
{
    const float* A = Aext ? Aext : bufsel(a_id);
    float* C = (Cext ? Cext : bufsel(c_id)) + c_off;

    __shared__ float As[16][64];
    __shared__ float Bs[16][64];
    int t  = threadIdx.x;
    int tx = t & 15;          // col group
    int ty = t >> 4;          // row group
    int bm0 = blockIdx.y * 64;
    int bn0 = blockIdx.x * 64;
    float acc[4][4];
    #pragma unroll
    for (int i = 0; i < 4; i++)
        #pragma unroll
        for (int j = 0; j < 4; j++) acc[i][j] = 0.f;

    int ar = t >> 2, ac = (t & 3) * 4;    // A tile: row 0..63, 4 cols
    int br = t >> 4, bc = (t & 15) * 4;   // B tile: row 0..15, 4 cols

    for (int k0 = 0; k0 < K; k0 += 16) {
        float4 av = make_float4(0.f, 0.f, 0.f, 0.f);
        if (bm0 + ar < M) av = *(const float4*)&A[(size_t)(bm0 + ar) * K + k0 + ac];
        As[ac + 0][ar] = av.x; As[ac + 1][ar] = av.y;
        As[ac + 2][ar] = av.z; As[ac + 3][ar] = av.w;
        float4 bv = *(const float4*)&B[(size_t)(k0 + br) * N + bn0 + bc];
        *(float4*)&Bs[br][bc] = bv;
        __syncthreads();
        #pragma unroll
        for (int kk = 0; kk < 16; kk++) {
            float4 a4 = *(float4*)&As[kk][ty * 4];
            float4 b4 = *(float4*)&Bs[kk][tx * 4];
            float ra[4] = {a4.x, a4.y, a4.z, a4.w};
            float rb[4] = {b4.x, b4.y, b4.z, b4.w};
            #pragma unroll
            for (int i = 0; i < 4; i++)
                #pragma unroll
                for (int j = 0; j < 4; j++)
                    acc[i][j] = fmaf(ra[i], rb[j], acc[i][j]);
        }
        __syncthreads();
    }
    #pragma unroll
    for (int i = 0; i < 4; i++) {
        int row = bm0 + ty * 4 + i;
        if (row >= M) continue;
        #pragma unroll
        for (int j = 0; j < 4; j++) {
            int col = bn0 + tx * 4 + j;
            float bz = bias ? bias[col] : 0.f;
            C[(size_t)row * N + col] = acc[i][j] + bz;
        }
    }
}

// ---------------- attention coefficients (H=8, D=64) ----------------
// one warp per (node, head): el = <ft[n,h,:], al[h,:]>, er likewise. ft = g_ft.
__global__ __launch_bounds__(256) void k_elr8(
    const float* __restrict__ al, const float* __restrict__ ar)
{
    int gw = (blockIdx.x * blockDim.x + threadIdx.x) >> 5;   // global warp = n*8+h
    int lane = threadIdx.x & 31;
    int n = gw >> 3, h = gw & 7;
    const float* fb = g_ft + (size_t)n * 512 + h * 64;
    float a = fb[lane], b = fb[lane + 32];
    float vl = a * al[h * 64 + lane] + b * al[h * 64 + lane + 32];
    float vr = a * ar[h * 64 + lane] + b * ar[h * 64 + lane + 32];
    #pragma unroll
    for (int o = 16; o > 0; o >>= 1) {
        vl += __shfl_xor_sync(0xffffffffu, vl, o);
        vr += __shfl_xor_sync(0xffffffffu, vr, o);
    }
    if (lane == 0) { g_el[gw] = vl; g_er[gw] = vr; }
}

// ---------------- per-edge raw attention logits ----------------
template <int H>
__global__ void k_edge_e(const int* __restrict__ src, const int* __restrict__ dst)
{
    int t = blockIdx.x * blockDim.x + threadIdx.x;
    if (t >= NEDGES * H) return;
    int eid = t / H, h = t % H;
    int s = src[eid], d = dst[eid];
    float x = g_el[s * H + h] + g_er[d * H + h];
    g_e[t] = (x >= 0.f) ? x : 0.2f * x;      // leaky_relu(0.2)
}

// ---------------- segment softmax over dst (in-place on g_e) ----------------
template <int H>
__global__ void k_softmax()
{
    int t = blockIdx.x * blockDim.x + threadIdx.x;
    if (t >= NNODES * H) return;
    int n = t / H, h = t % H;
    int s0 = g_rowoff[n], s1 = g_rowoff[n + 1];
    float m = -1e30f;
    for (int p = s0; p < s1; p++) m = fmaxf(m, g_e[g_eid[p] * H + h]);
    float sum = 0.f;
    for (int p = s0; p < s1; p++) {
        int idx = g_eid[p] * H + h;
        float ex = expf(g_e[idx] - m);
        g_e[idx] = ex;
        sum += ex;
    }
    float inv = 1.f / (sum + 1e-16f);
    for (int p = s0; p < s1; p++) g_e[g_eid[p] * H + h] *= inv;
}

// ---------------- aggregation, F=512, H=8: block(128) per dst node ----------------
__global__ __launch_bounds__(128) void k_agg512(
    const int* __restrict__ src,
    const float* __restrict__ bias, int use_resid,
    float* __restrict__ out_ext)
{
    const float* ft = g_ft;
    float* out = out_ext ? out_ext : g_h1;
    int n = blockIdx.x;
    int t = threadIdx.x;
    int f = t * 4;
    int h = f >> 6;
    float4 acc = *(const float4*)&bias[f];
    if (use_resid) {
        float4 r = *(const float4*)&g_h1[(size_t)n * 512 + f];
        acc.x += r.x; acc.y += r.y; acc.z += r.z; acc.w += r.w;
    }
    int s0 = g_rowoff[n], s1 = g_rowoff[n + 1];
    for (int p = s0; p < s1; p++) {
        int eid = g_eid[p];
        float w = g_e[(size_t)eid * 8 + h];
        int s = src[eid];
        float4 v = *(const float4*)&ft[(size_t)s * 512 + f];
        acc.x = fmaf(w, v.x, acc.x);
        acc.y = fmaf(w, v.y, acc.y);
        acc.z = fmaf(w, v.z, acc.z);
        acc.w = fmaf(w, v.w, acc.w);
    }
    // elu
    acc.x = (acc.x > 0.f) ? acc.x : expm1f(acc.x);
    acc.y = (acc.y > 0.f) ? acc.y : expm1f(acc.y);
    acc.z = (acc.z > 0.f) ? acc.z : expm1f(acc.z);
    acc.w = (acc.w > 0.f) ? acc.w : expm1f(acc.w);
    *(float4*)&out[(size_t)n * 512 + f] = acc;
}

// ---------------- layer-2 projections: ft2 = h2@W2, res2 = h2@resW2, fused el/er ----------------
__global__ __launch_bounds__(32) void k_l2proj(
    const float* __restrict__ h2, const float* __restrict__ W2,
    const float* __restrict__ resW2, const float* __restrict__ al2,
    const float* __restrict__ ar2)
{
    int n = blockIdx.x;
    int lane = threadIdx.x;
    float a1 = 0.f, a2 = 0.f;
    const float* hr = h2 + (size_t)n * 512;
    if (lane < 16) {
        #pragma unroll 8
        for (int k = 0; k < 512; k++) {
            float hv = hr[k];
            a1 = fmaf(hv, W2[k * 16 + lane], a1);
            a2 = fmaf(hv, resW2[k * 16 + lane], a2);
        }
    }
    float el_p = (lane < 16) ? a1 * al2[lane] : 0.f;
    float er_p = (lane < 16) ? a1 * ar2[lane] : 0.f;
    #pragma unroll
    for (int o = 16; o > 0; o >>= 1) {
        el_p += __shfl_xor_sync(0xffffffffu, el_p, o);
        er_p += __shfl_xor_sync(0xffffffffu, er_p, o);
    }
    if (lane == 0) { g_el[n] = el_p; g_er[n] = er_p; }  // stride-1 reuse for H=1
    if (lane < 16) { g_ft2[n * 16 + lane] = a1; g_res2[n * 16 + lane] = a2; }
}

// ---------------- aggregation F=16, H=1 + linear residual + bias -> logits ----------------
__global__ __launch_bounds__(32) void k_agg16(
    const int* __restrict__ src, const float* __restrict__ b2,
    float* __restrict__ logits)
{
    int n = blockIdx.x;
    int lane = threadIdx.x;
    if (lane >= 16) return;
    float acc = g_res2[n * 16 + lane] + b2[lane];
    int s0 = g_rowoff[n], s1 = g_rowoff[n + 1];
    for (int p = s0; p < s1; p++) {
        int eid = g_eid[p];
        float w = g_e[eid];
        int s = src[eid];
        acc = fmaf(w, g_ft2[s * 16 + lane], acc);
    }
    logits[n * 16 + lane] = acc;
}

// ---------------- launch (ONLY kernel launches — graph-capturable) ----------------
extern "C" void kernel_launch(void* const* d_in, const int* in_sizes, int n_in,
                              void* d_out, int out_size)
{
    const float* x0    = (const float*)d_in[0];
    const float* x1    = (const float*)d_in[1];
    const int*   src   = (const int*)d_in[2];     // int32 (harness dtype set: f32/i32/bf16)
    const int*   dst   = (const int*)d_in[3];
    const float* fc0_W = (const float*)d_in[4];
    const float* fc0_b = (const float*)d_in[5];
    const float* fc1_W = (const float*)d_in[6];
    const float* fc1_b = (const float*)d_in[7];
    const float* W0  = (const float*)d_in[8];
    const float* al0 = (const float*)d_in[9];
    const float* ar0 = (const float*)d_in[10];
    const float* b0  = (const float*)d_in[11];
    const float* W1  = (const float*)d_in[12];
    const float* al1 = (const float*)d_in[13];
    const float* ar1 = (const float*)d_in[14];
    const float* b1  = (const float*)d_in[15];
    const float* W2  = (const float*)d_in[16];
    const float* al2 = (const float*)d_in[17];
    const float* ar2 = (const float*)d_in[18];
    const float* b2  = (const float*)d_in[19];
    const float* resW2 = (const float*)d_in[20];

    float* out    = (float*)d_out;
    float* logits = out;                         // [50000,16]
    float* enc    = out + (size_t)NNODES * 16;   // [50000,512]

    // ---- CSR build (graph is identical across layers) ----
    k_zero_counts<<<(NNODES + 255) / 256, 256>>>();
    k_count<<<(NEDGES + 255) / 256, 256>>>(dst);
    k_scan<<<1, 1024>>>();
    k_scatter<<<(NEDGES + 255) / 256, 256>>>(dst);
    k_sortseg<<<(NNODES + 255) / 256, 256>>>();

    // ---- per-type input projections (write into g_h0) ----
    dim3 gfc(1, (NHALF + 63) / 64);
    gemm_kernel<<<gfc, 256>>>(x0, -1, nullptr, 0, 0,                  fc0_W, NHALF, 64, 256, fc0_b);
    gemm_kernel<<<gfc, 256>>>(x1, -1, nullptr, 0, (size_t)NHALF * 64, fc1_W, NHALF, 64, 256, fc1_b);

    // ---- layer 0: 64 -> 8x64, elu ----
    dim3 g0(512 / 64, (NNODES + 63) / 64);
    gemm_kernel<<<g0, 256>>>(nullptr, 0, nullptr, 1, 0, W0, NNODES, 512, 64, nullptr);
    k_elr8<<<NNODES, 256>>>(al0, ar0);
    k_edge_e<8><<<(NEDGES * 8 + 255) / 256, 256>>>(src, dst);
    k_softmax<8><<<(NNODES * 8 + 255) / 256, 256>>>();
    k_agg512<<<NNODES, 128>>>(src, b0, 0, nullptr);   // -> g_h1

    // ---- layer 1: 512 -> 8x64, identity residual, elu -> encoded ----
    gemm_kernel<<<g0, 256>>>(nullptr, 2, nullptr, 1, 0, W1, NNODES, 512, 512, nullptr);
    k_elr8<<<NNODES, 256>>>(al1, ar1);
    k_edge_e<8><<<(NEDGES * 8 + 255) / 256, 256>>>(src, dst);
    k_softmax<8><<<(NNODES * 8 + 255) / 256, 256>>>();
    k_agg512<<<NNODES, 128>>>(src, b1, 1, enc);       // resid=g_h1 -> enc

    // ---- output layer: 512 -> 1x16, linear residual, no act ----
    k_l2proj<<<NNODES, 32>>>(enc, W2, resW2, al2, ar2);
    k_edge_e<1><<<(NEDGES + 255) / 256, 256>>>(src, dst);
    k_softmax<1><<<(NNODES + 255) / 256, 256>>>();
    k_agg16<<<NNODES, 32>>>(src, b2, logits);
}